// round 15
// baseline (speedup 1.0000x reference)
#include <cuda_runtime.h>
#include <cuda_bf16.h>
#include <math.h>
#include <stdint.h>

#define BATCH 16
#define CIN   256
#define HW    4096      // 64*64
#define DOWN  1024      // 32*32
#define C8    32
#define C2    128
#define MCONV 192       // 32 + 32 + 128
#define NCHUNK 64       // l-chunks for column sum partials (64 rows each)

// ---------------- scratch (device globals; no allocation allowed) ----------------
__device__ float g_w   [MCONV * CIN];
__device__ float g_bias[MCONV];
__device__ float g_q   [BATCH * C8 * HW];
__device__ float g_kp  [BATCH * C8 * DOWN];
__device__ float g_vp  [BATCH * C2 * DOWN];
__device__ __nv_bfloat16 g_attn[(size_t)BATCH * HW * DOWN];  // 134 MB: P = exp(logit)
__device__ float g_ps  [BATCH * NCHUNK * DOWN];              // partial sums of P
__device__ float g_csumr[BATCH * DOWN];
__device__ float g_app [BATCH * HW * C2];

// ---------------- helpers --------------------------------------------------------
__device__ __forceinline__ uint32_t f2tf32(float v) {
    uint32_t r;
    asm("cvt.rna.tf32.f32 %0, %1;" : "=r"(r) : "f"(v));
    return r;
}
__device__ __forceinline__ void mma_tf32(float* d, const uint32_t* a, const uint32_t* b) {
    asm volatile(
        "mma.sync.aligned.m16n8k8.row.col.f32.tf32.tf32.f32 "
        "{%0,%1,%2,%3}, {%4,%5,%6,%7}, {%8,%9}, {%0,%1,%2,%3};"
        : "+f"(d[0]), "+f"(d[1]), "+f"(d[2]), "+f"(d[3])
        : "r"(a[0]), "r"(a[1]), "r"(a[2]), "r"(a[3]), "r"(b[0]), "r"(b[1]));
}
__device__ __forceinline__ void mma_bf16(float* d, const uint32_t* a, const uint32_t* b) {
    asm volatile(
        "mma.sync.aligned.m16n8k16.row.col.f32.bf16.bf16.f32 "
        "{%0,%1,%2,%3}, {%4,%5,%6,%7}, {%8,%9}, {%0,%1,%2,%3};"
        : "+f"(d[0]), "+f"(d[1]), "+f"(d[2]), "+f"(d[3])
        : "r"(a[0]), "r"(a[1]), "r"(a[2]), "r"(a[3]), "r"(b[0]), "r"(b[1]));
}
#define FU(x) __float_as_uint(x)

// ---------------- K0: pack conv weights ------------------------------------------
__global__ void k_pack(const float* __restrict__ qw, const float* __restrict__ qb,
                       const float* __restrict__ kw, const float* __restrict__ kb,
                       const float* __restrict__ vw, const float* __restrict__ vb) {
    int i = blockIdx.x * 256 + threadIdx.x;
    if (i < MCONV * CIN) {
        int r = i >> 8, c = i & 255;
        float v;
        if (r < 32)      v = qw[r * CIN + c];
        else if (r < 64) v = kw[(r - 32) * CIN + c];
        else             v = vw[(r - 64) * CIN + c];
        g_w[i] = v;
    }
    if (i < MCONV)
        g_bias[i] = (i < 32) ? qb[i] : (i < 64) ? kb[i - 32] : vb[i - 64];
}

// ---------------- K1: fused q/k/v convs + INLINE 2x2 MAXPOOL for k/v -------------
__global__ __launch_bounds__(256) void k_conv_mma(const float* __restrict__ x) {
    __shared__ float sA[64][36];    // W tile [m][k]
    __shared__ float sB[32][136];   // X tile [k][n]
    __shared__ float sPool[64][36]; // lower-half pair-max exchange

    const int b  = blockIdx.z;
    const int m0 = blockIdx.y * 64;
    const int n0 = blockIdx.x * 128;
    const float* X = x + (size_t)b * CIN * HW;

    const int tid  = threadIdx.x;
    const int wid  = tid >> 5;
    const int lane = tid & 31;
    const int qid  = lane >> 2;
    const int qtr  = lane & 3;
    const int wm   = (wid >> 2) * 32;
    const int wn   = (wid & 3) * 32;

    float acc[2][4][4] = {};

    for (int k0 = 0; k0 < CIN; k0 += 32) {
        #pragma unroll
        for (int it = 0; it < 2; it++) {
            int f = tid + it * 256;
            int m = f >> 3, k4 = (f & 7) * 4;
            float4 a4 = *(const float4*)&g_w[(m0 + m) * CIN + k0 + k4];
            uint32_t* dp = (uint32_t*)&sA[m][k4];
            dp[0] = f2tf32(a4.x); dp[1] = f2tf32(a4.y);
            dp[2] = f2tf32(a4.z); dp[3] = f2tf32(a4.w);
        }
        #pragma unroll
        for (int it = 0; it < 4; it++) {
            int f = tid + it * 256;
            int kk = f >> 5, n4 = (f & 31) * 4;
            float4 b4 = *(const float4*)&X[(size_t)(k0 + kk) * HW + n0 + n4];
            uint32_t* dp = (uint32_t*)&sB[kk][n4];
            dp[0] = f2tf32(b4.x); dp[1] = f2tf32(b4.y);
            dp[2] = f2tf32(b4.z); dp[3] = f2tf32(b4.w);
        }
        __syncthreads();

        #pragma unroll
        for (int ks = 0; ks < 4; ks++) {
            const int kk = ks * 8;
            uint32_t af[2][4], bf[4][2];
            #pragma unroll
            for (int ma = 0; ma < 2; ma++) {
                int r = wm + ma * 16 + qid;
                af[ma][0] = FU(sA[r    ][kk + qtr]);
                af[ma][1] = FU(sA[r + 8][kk + qtr]);
                af[ma][2] = FU(sA[r    ][kk + qtr + 4]);
                af[ma][3] = FU(sA[r + 8][kk + qtr + 4]);
            }
            #pragma unroll
            for (int na = 0; na < 4; na++) {
                int c = wn + na * 8 + qid;
                bf[na][0] = FU(sB[kk + qtr    ][c]);
                bf[na][1] = FU(sB[kk + qtr + 4][c]);
            }
            #pragma unroll
            for (int ma = 0; ma < 2; ma++)
                #pragma unroll
                for (int na = 0; na < 4; na++)
                    mma_tf32(acc[ma][na], af[ma], bf[na]);
        }
        __syncthreads();
    }

    // ---- epilogue phase 1: q direct stores + lower-half (h0 row) pool partials --
    #pragma unroll
    for (int ma = 0; ma < 2; ma++) {
        #pragma unroll
        for (int half = 0; half < 2; half++) {
            int rl = wm + ma * 16 + qid + half * 8;   // row in tile 0..63
            int m  = m0 + rl;
            float bias = g_bias[m];
            if (m < 32) {
                float* dst = g_q + ((size_t)b * C8 + m) * HW;
                #pragma unroll
                for (int na = 0; na < 4; na++) {
                    int c = n0 + wn + na * 8 + 2 * qtr;
                    float2 o;
                    o.x = acc[ma][na][half * 2 + 0] + bias;
                    o.y = acc[ma][na][half * 2 + 1] + bias;
                    *(float2*)&dst[c] = o;
                }
            } else if (wn < 64) {
                #pragma unroll
                for (int na = 0; na < 4; na++) {
                    float vx = acc[ma][na][half * 2 + 0] + bias;
                    float vy = acc[ma][na][half * 2 + 1] + bias;
                    sPool[rl][(wn >> 1) + na * 4 + qtr] = fmaxf(vx, vy);
                }
            }
        }
    }
    __syncthreads();

    // ---- epilogue phase 2: upper-half (h0+1 row) combine + pooled store ---------
    if (wn >= 64) {
        const int p0 = (n0 >> 7) * 32;   // ph * 32
        #pragma unroll
        for (int ma = 0; ma < 2; ma++) {
            #pragma unroll
            for (int half = 0; half < 2; half++) {
                int rl = wm + ma * 16 + qid + half * 8;
                int m  = m0 + rl;
                if (m < 32) continue;
                float bias = g_bias[m];
                float* dst = (m < 64)
                    ? g_kp + ((size_t)b * C8 + (m - 32)) * DOWN
                    : g_vp + ((size_t)b * C2 + (m - 64)) * DOWN;
                #pragma unroll
                for (int na = 0; na < 4; na++) {
                    int pw = ((wn - 64) >> 1) + na * 4 + qtr;
                    float vx = acc[ma][na][half * 2 + 0] + bias;
                    float vy = acc[ma][na][half * 2 + 1] + bias;
                    float pm = fmaxf(fmaxf(vx, vy), sPool[rl][pw]);
                    dst[p0 + pw] = pm;
                }
            }
        }
    }
}

// ---------------- K3a: P = exp(Q @ K^T) stored bf16, tile 128l x 128j, 8x8/thread
__global__ __launch_bounds__(256, 2) void k_attn() {
    const int b  = blockIdx.z;
    const int l0 = blockIdx.y * 128;
    const int j0 = blockIdx.x * 128;

    const float* Q  = g_q  + (size_t)b * (C8 * HW);    // viewed [4096][32]
    const float* Km = g_kp + (size_t)b * (C8 * DOWN);  // viewed [1024][32]

    __shared__ float Qs[32][132];   // [d][l]
    __shared__ float Ks[32][132];   // [d][j]

    const int tid = threadIdx.x;
    const int tx = tid & 15;        // j: tx*8
    const int ty = tid >> 4;        // l: ty*8

    #pragma unroll
    for (int it = 0; it < 4; it++) {
        int idx = tid + it * 256;
        int lr = idx >> 3, lc = (idx & 7) * 4;
        float4 a = *(const float4*)&Q[(size_t)(l0 + lr) * 32 + lc];
        Qs[lc + 0][lr] = a.x; Qs[lc + 1][lr] = a.y;
        Qs[lc + 2][lr] = a.z; Qs[lc + 3][lr] = a.w;
    }
    #pragma unroll
    for (int it = 0; it < 4; it++) {
        int idx = tid + it * 256;
        int jr = idx >> 3, jc = (idx & 7) * 4;
        float4 k4 = *(const float4*)&Km[(size_t)(j0 + jr) * 32 + jc];
        Ks[jc + 0][jr] = k4.x; Ks[jc + 1][jr] = k4.y;
        Ks[jc + 2][jr] = k4.z; Ks[jc + 3][jr] = k4.w;
    }
    __syncthreads();

    float acc[8][8] = {};
    #pragma unroll
    for (int d = 0; d < 32; d++) {
        float a[8], bb[8];
        *(float4*)&a[0]  = *(const float4*)&Qs[d][ty * 8];
        *(float4*)&a[4]  = *(const float4*)&Qs[d][ty * 8 + 4];
        *(float4*)&bb[0] = *(const float4*)&Ks[d][tx * 8];
        *(float4*)&bb[4] = *(const float4*)&Ks[d][tx * 8 + 4];
        #pragma unroll
        for (int i = 0; i < 8; i++)
            #pragma unroll
            for (int j = 0; j < 8; j++)
                acc[i][j] += a[i] * bb[j];
    }

    __nv_bfloat16* C = g_attn + ((size_t)b * HW + l0) * DOWN + j0;
    #pragma unroll
    for (int i = 0; i < 8; i++) {
        __nv_bfloat162 p0 = __floats2bfloat162_rn(__expf(acc[i][0]), __expf(acc[i][1]));
        __nv_bfloat162 p1 = __floats2bfloat162_rn(__expf(acc[i][2]), __expf(acc[i][3]));
        __nv_bfloat162 p2 = __floats2bfloat162_rn(__expf(acc[i][4]), __expf(acc[i][5]));
        __nv_bfloat162 p3 = __floats2bfloat162_rn(__expf(acc[i][6]), __expf(acc[i][7]));
        uint4 o;
        o.x = *(uint32_t*)&p0;
        o.y = *(uint32_t*)&p1;
        o.z = *(uint32_t*)&p2;
        o.w = *(uint32_t*)&p3;
        *(uint4*)&C[(size_t)(ty * 8 + i) * DOWN + tx * 8] = o;
    }
}

// ---------------- K3b: per-column partial sums of P (pure sum, bf16 in) ----------
__global__ void k_stats1() {
    const int b  = blockIdx.z;
    const int ck = blockIdx.y;
    const int j2 = blockIdx.x * 256 + threadIdx.x;   // column pair 0..511
    const int lsz = HW / NCHUNK;                     // 64
    const __nv_bfloat162* A = (const __nv_bfloat162*)(g_attn
        + (size_t)b * HW * DOWN + (size_t)ck * lsz * DOWN) + j2;
    float2 s0 = {0.f, 0.f}, s1 = {0.f, 0.f}, s2 = {0.f, 0.f}, s3 = {0.f, 0.f};
    #pragma unroll 4
    for (int l = 0; l < lsz; l += 4) {
        float2 a = __bfloat1622float2(A[(size_t)(l + 0) * (DOWN / 2)]);
        float2 bvv = __bfloat1622float2(A[(size_t)(l + 1) * (DOWN / 2)]);
        float2 c = __bfloat1622float2(A[(size_t)(l + 2) * (DOWN / 2)]);
        float2 d = __bfloat1622float2(A[(size_t)(l + 3) * (DOWN / 2)]);
        s0.x += a.x; s0.y += a.y;
        s1.x += bvv.x; s1.y += bvv.y;
        s2.x += c.x; s2.y += c.y;
        s3.x += d.x; s3.y += d.y;
    }
    float2 o;
    o.x = (s0.x + s1.x) + (s2.x + s3.x);
    o.y = (s0.y + s1.y) + (s2.y + s3.y);
    *(float2*)&g_ps[(b * NCHUNK + ck) * DOWN + j2 * 2] = o;
}

__global__ void k_stats2() {
    const int b = blockIdx.y;
    const int j = blockIdx.x * 256 + threadIdx.x;
    float S = 0.f;
    #pragma unroll 8
    for (int c = 0; c < NCHUNK; c++)
        S += g_ps[(b * NCHUNK + c) * DOWN + j];
    g_csumr[b * DOWN + j] = 1.f / S;
}

// ---------------- K4: applied = P @ (V/S) via mma.sync bf16 m16n8k16 -------------
__global__ __launch_bounds__(256, 2) void k_apply_mma() {
    __shared__ __nv_bfloat16 sP[128][40];   // [l][j in chunk]
    __shared__ __nv_bfloat16 sB[128][40];   // [c][j in chunk]

    const int b   = blockIdx.y;
    const int l0  = blockIdx.x * 128;
    const int tid = threadIdx.x;
    const int wid = tid >> 5;
    const int lane = tid & 31;
    const int qid = lane >> 2;
    const int qtr = lane & 3;
    const int wm = (wid >> 2) * 64;
    const int wn = (wid & 3) * 32;

    const __nv_bfloat16* A = g_attn + ((size_t)b * HW + l0) * DOWN;
    const float* V  = g_vp   + (size_t)b * (C2 * DOWN);
    const float* cs = g_csumr + b * DOWN;

    float acc[4][4][4] = {};

    for (int j0 = 0; j0 < DOWN; j0 += 32) {
        #pragma unroll
        for (int it = 0; it < 4; it++) {
            int idx = tid + it * 256;
            int l = idx >> 3, jq = (idx & 7) * 4;
            uint2 v = *(const uint2*)&A[(size_t)l * DOWN + j0 + jq];
            *(uint2*)&sP[l][jq] = v;
        }
        #pragma unroll
        for (int it = 0; it < 4; it++) {
            int idx = tid + it * 256;
            int c = idx & 127, j4 = idx >> 7;     // j4 in 0..7
            float4 s4 = *(const float4*)&cs[j0 + j4 * 4];
            __nv_bfloat162 p0 = __floats2bfloat162_rn(
                V[(size_t)(j0 + j4 * 4 + 0) * C2 + c] * s4.x,
                V[(size_t)(j0 + j4 * 4 + 1) * C2 + c] * s4.y);
            __nv_bfloat162 p1 = __floats2bfloat162_rn(
                V[(size_t)(j0 + j4 * 4 + 2) * C2 + c] * s4.z,
                V[(size_t)(j0 + j4 * 4 + 3) * C2 + c] * s4.w);
            uint2 o;
            o.x = *(uint32_t*)&p0;
            o.y = *(uint32_t*)&p1;
            *(uint2*)&sB[c][j4 * 4] = o;
        }
        __syncthreads();

        #pragma unroll
        for (int ks = 0; ks < 2; ks++) {
            const int kb = ks * 16;
            uint32_t bfr[4][2];
            #pragma unroll
            for (int na = 0; na < 4; na++) {
                int c = wn + na * 8 + qid;
                bfr[na][0] = *(const uint32_t*)&sB[c][kb + qtr * 2];
                bfr[na][1] = *(const uint32_t*)&sB[c][kb + 8 + qtr * 2];
            }
            #pragma unroll
            for (int ma = 0; ma < 4; ma++) {
                int r = wm + ma * 16 + qid;
                uint32_t af[4];
                af[0] = *(const uint32_t*)&sP[r    ][kb + qtr * 2];
                af[1] = *(const uint32_t*)&sP[r + 8][kb + qtr * 2];
                af[2] = *(const uint32_t*)&sP[r    ][kb + 8 + qtr * 2];
                af[3] = *(const uint32_t*)&sP[r + 8][kb + 8 + qtr * 2];
                #pragma unroll
                for (int na = 0; na < 4; na++)
                    mma_bf16(acc[ma][na], af, bfr[na]);
            }
        }
        __syncthreads();
    }

    float* O = g_app + ((size_t)b * HW + l0) * C2;
    #pragma unroll
    for (int ma = 0; ma < 4; ma++) {
        int r = wm + ma * 16 + qid;
        #pragma unroll
        for (int na = 0; na < 4; na++) {
            int c = wn + na * 8 + 2 * qtr;
            float2 lo, hi;
            lo.x = acc[ma][na][0]; lo.y = acc[ma][na][1];
            hi.x = acc[ma][na][2]; hi.y = acc[ma][na][3];
            *(float2*)&O[(size_t)r * C2 + c]       = lo;
            *(float2*)&O[(size_t)(r + 8) * C2 + c] = hi;
        }
    }
}

// ---------------- K5: out = gamma*(W2 @ applied_r + b2) + x via mma tf32 ---------
__global__ __launch_bounds__(256) void k_out_mma(const float* __restrict__ w2,
                                                 const float* __restrict__ b2,
                                                 const float* __restrict__ gamma,
                                                 const float* __restrict__ x,
                                                 float* __restrict__ out) {
    __shared__ float sA[64][36];
    __shared__ float sB[32][136];

    const int b  = blockIdx.z;
    const int m0 = blockIdx.y * 64;
    const int n0 = blockIdx.x * 128;
    const float* Bm = g_app + (size_t)b * (HW * C2);   // viewed [128][4096]

    const int tid  = threadIdx.x;
    const int wid  = tid >> 5;
    const int lane = tid & 31;
    const int qid  = lane >> 2;
    const int qtr  = lane & 3;
    const int wm   = (wid >> 2) * 32;
    const int wn   = (wid & 3) * 32;

    float acc[2][4][4] = {};

    for (int k0 = 0; k0 < C2; k0 += 32) {
        #pragma unroll
        for (int it = 0; it < 2; it++) {
            int f = tid + it * 256;
            int m = f >> 3, k4 = (f & 7) * 4;
            float4 a4 = *(const float4*)&w2[(m0 + m) * C2 + k0 + k4];
            uint32_t* dp = (uint32_t*)&sA[m][k4];
            dp[0] = f2tf32(a4.x); dp[1] = f2tf32(a4.y);
            dp[2] = f2tf32(a4.z); dp[3] = f2tf32(a4.w);
        }
        #pragma unroll
        for (int it = 0; it < 4; it++) {
            int f = tid + it * 256;
            int kk = f >> 5, n4 = (f & 31) * 4;
            float4 b4 = *(const float4*)&Bm[(size_t)(k0 + kk) * HW + n0 + n4];
            uint32_t* dp = (uint32_t*)&sB[kk][n4];
            dp[0] = f2tf32(b4.x); dp[1] = f2tf32(b4.y);
            dp[2] = f2tf32(b4.z); dp[3] = f2tf32(b4.w);
        }
        __syncthreads();

        #pragma unroll
        for (int ks = 0; ks < 4; ks++) {
            const int kk = ks * 8;
            uint32_t af[2][4], bf[4][2];
            #pragma unroll
            for (int ma = 0; ma < 2; ma++) {
                int r = wm + ma * 16 + qid;
                af[ma][0] = FU(sA[r    ][kk + qtr]);
                af[ma][1] = FU(sA[r + 8][kk + qtr]);
                af[ma][2] = FU(sA[r    ][kk + qtr + 4]);
                af[ma][3] = FU(sA[r + 8][kk + qtr + 4]);
            }
            #pragma unroll
            for (int na = 0; na < 4; na++) {
                int c = wn + na * 8 + qid;
                bf[na][0] = FU(sB[kk + qtr    ][c]);
                bf[na][1] = FU(sB[kk + qtr + 4][c]);
            }
            #pragma unroll
            for (int ma = 0; ma < 2; ma++)
                #pragma unroll
                for (int na = 0; na < 4; na++)
                    mma_tf32(acc[ma][na], af[ma], bf[na]);
        }
        __syncthreads();
    }

    const float g = __ldg(gamma);
    #pragma unroll
    for (int ma = 0; ma < 2; ma++) {
        #pragma unroll
        for (int half = 0; half < 2; half++) {
            int m = m0 + wm + ma * 16 + qid + half * 8;
            float bias = b2[m];
            #pragma unroll
            for (int na = 0; na < 4; na++) {
                int c = n0 + wn + na * 8 + 2 * qtr;
                size_t base = ((size_t)b * 256 + m) * HW + c;
                float2 xi = *(const float2*)&x[base];
                float2 o;
                o.x = g * (acc[ma][na][half * 2 + 0] + bias) + xi.x;
                o.y = g * (acc[ma][na][half * 2 + 1] + bias) + xi.y;
                *(float2*)&out[base] = o;
            }
        }
    }
}

// ---------------- launch ---------------------------------------------------------
extern "C" void kernel_launch(void* const* d_in, const int* in_sizes, int n_in,
                              void* d_out, int out_size) {
    const float* x  = (const float*)d_in[0];
    const float* qw = (const float*)d_in[1];
    const float* qb = (const float*)d_in[2];
    const float* kw = (const float*)d_in[3];
    const float* kb = (const float*)d_in[4];
    const float* vw = (const float*)d_in[5];
    const float* vb = (const float*)d_in[6];
    const float* w2 = (const float*)d_in[7];
    const float* b2 = (const float*)d_in[8];
    const float* gm = (const float*)d_in[9];
    float* out = (float*)d_out;

    k_pack<<<(MCONV * CIN + 255) / 256, 256>>>(qw, qb, kw, kb, vw, vb);
    k_conv_mma<<<dim3(HW / 128, MCONV / 64, BATCH), 256>>>(x);
    k_attn<<<dim3(DOWN / 128, HW / 128, BATCH), 256>>>();
    k_stats1<<<dim3(DOWN / 2 / 256, NCHUNK, BATCH), 256>>>();
    k_stats2<<<dim3(DOWN / 256, BATCH), 256>>>();
    k_apply_mma<<<dim3(HW / 128, BATCH), 256>>>();
    k_out_mma<<<dim3(HW / 128, 256 / 64, BATCH), 256>>>(w2, b2, gm, x, out);
}

// round 16
// speedup vs baseline: 1.0902x; 1.0902x over previous
#include <cuda_runtime.h>
#include <cuda_bf16.h>
#include <math.h>
#include <stdint.h>

#define BATCH 16
#define CIN   256
#define HW    4096      // 64*64
#define DOWN  1024      // 32*32
#define C8    32
#define C2    128
#define MCONV 192       // 32 + 32 + 128
#define NCHUNK 64       // l-chunks for column sum partials (one per attn CTA row-tile)

// ---------------- scratch (device globals; no allocation allowed) ----------------
__device__ float g_w   [MCONV * CIN];
__device__ float g_bias[MCONV];
__device__ float g_q   [BATCH * C8 * HW];
__device__ float g_kp  [BATCH * C8 * DOWN];
__device__ float g_vp  [BATCH * C2 * DOWN];
__device__ __nv_bfloat16 g_attn[(size_t)BATCH * HW * DOWN];  // 134 MB: P = exp(logit)
__device__ float g_ps  [BATCH * NCHUNK * DOWN];              // partial sums of P
__device__ float g_csumr[BATCH * DOWN];
__device__ float g_app [BATCH * HW * C2];

// ---------------- helpers --------------------------------------------------------
__device__ __forceinline__ uint32_t f2tf32(float v) {
    uint32_t r;
    asm("cvt.rna.tf32.f32 %0, %1;" : "=r"(r) : "f"(v));
    return r;
}
__device__ __forceinline__ void mma_tf32(float* d, const uint32_t* a, const uint32_t* b) {
    asm volatile(
        "mma.sync.aligned.m16n8k8.row.col.f32.tf32.tf32.f32 "
        "{%0,%1,%2,%3}, {%4,%5,%6,%7}, {%8,%9}, {%0,%1,%2,%3};"
        : "+f"(d[0]), "+f"(d[1]), "+f"(d[2]), "+f"(d[3])
        : "r"(a[0]), "r"(a[1]), "r"(a[2]), "r"(a[3]), "r"(b[0]), "r"(b[1]));
}
__device__ __forceinline__ void mma_bf16(float* d, const uint32_t* a, const uint32_t* b) {
    asm volatile(
        "mma.sync.aligned.m16n8k16.row.col.f32.bf16.bf16.f32 "
        "{%0,%1,%2,%3}, {%4,%5,%6,%7}, {%8,%9}, {%0,%1,%2,%3};"
        : "+f"(d[0]), "+f"(d[1]), "+f"(d[2]), "+f"(d[3])
        : "r"(a[0]), "r"(a[1]), "r"(a[2]), "r"(a[3]), "r"(b[0]), "r"(b[1]));
}
#define FU(x) __float_as_uint(x)

// ---------------- K0: pack conv weights ------------------------------------------
__global__ void k_pack(const float* __restrict__ qw, const float* __restrict__ qb,
                       const float* __restrict__ kw, const float* __restrict__ kb,
                       const float* __restrict__ vw, const float* __restrict__ vb) {
    int i = blockIdx.x * 256 + threadIdx.x;
    if (i < MCONV * CIN) {
        int r = i >> 8, c = i & 255;
        float v;
        if (r < 32)      v = qw[r * CIN + c];
        else if (r < 64) v = kw[(r - 32) * CIN + c];
        else             v = vw[(r - 64) * CIN + c];
        g_w[i] = v;
    }
    if (i < MCONV)
        g_bias[i] = (i < 32) ? qb[i] : (i < 64) ? kb[i - 32] : vb[i - 64];
}

// ---------------- K1: fused q/k/v convs + INLINE 2x2 MAXPOOL for k/v -------------
__global__ __launch_bounds__(256) void k_conv_mma(const float* __restrict__ x) {
    __shared__ float sA[64][36];    // W tile [m][k]
    __shared__ float sB[32][136];   // X tile [k][n]
    __shared__ float sPool[64][36]; // lower-half pair-max exchange

    const int b  = blockIdx.z;
    const int m0 = blockIdx.y * 64;
    const int n0 = blockIdx.x * 128;
    const float* X = x + (size_t)b * CIN * HW;

    const int tid  = threadIdx.x;
    const int wid  = tid >> 5;
    const int lane = tid & 31;
    const int qid  = lane >> 2;
    const int qtr  = lane & 3;
    const int wm   = (wid >> 2) * 32;
    const int wn   = (wid & 3) * 32;

    float acc[2][4][4] = {};

    for (int k0 = 0; k0 < CIN; k0 += 32) {
        #pragma unroll
        for (int it = 0; it < 2; it++) {
            int f = tid + it * 256;
            int m = f >> 3, k4 = (f & 7) * 4;
            float4 a4 = *(const float4*)&g_w[(m0 + m) * CIN + k0 + k4];
            uint32_t* dp = (uint32_t*)&sA[m][k4];
            dp[0] = f2tf32(a4.x); dp[1] = f2tf32(a4.y);
            dp[2] = f2tf32(a4.z); dp[3] = f2tf32(a4.w);
        }
        #pragma unroll
        for (int it = 0; it < 4; it++) {
            int f = tid + it * 256;
            int kk = f >> 5, n4 = (f & 31) * 4;
            float4 b4 = *(const float4*)&X[(size_t)(k0 + kk) * HW + n0 + n4];
            uint32_t* dp = (uint32_t*)&sB[kk][n4];
            dp[0] = f2tf32(b4.x); dp[1] = f2tf32(b4.y);
            dp[2] = f2tf32(b4.z); dp[3] = f2tf32(b4.w);
        }
        __syncthreads();

        #pragma unroll
        for (int ks = 0; ks < 4; ks++) {
            const int kk = ks * 8;
            uint32_t af[2][4], bf[4][2];
            #pragma unroll
            for (int ma = 0; ma < 2; ma++) {
                int r = wm + ma * 16 + qid;
                af[ma][0] = FU(sA[r    ][kk + qtr]);
                af[ma][1] = FU(sA[r + 8][kk + qtr]);
                af[ma][2] = FU(sA[r    ][kk + qtr + 4]);
                af[ma][3] = FU(sA[r + 8][kk + qtr + 4]);
            }
            #pragma unroll
            for (int na = 0; na < 4; na++) {
                int c = wn + na * 8 + qid;
                bf[na][0] = FU(sB[kk + qtr    ][c]);
                bf[na][1] = FU(sB[kk + qtr + 4][c]);
            }
            #pragma unroll
            for (int ma = 0; ma < 2; ma++)
                #pragma unroll
                for (int na = 0; na < 4; na++)
                    mma_tf32(acc[ma][na], af[ma], bf[na]);
        }
        __syncthreads();
    }

    // ---- epilogue phase 1: q direct stores + lower-half (h0 row) pool partials --
    #pragma unroll
    for (int ma = 0; ma < 2; ma++) {
        #pragma unroll
        for (int half = 0; half < 2; half++) {
            int rl = wm + ma * 16 + qid + half * 8;   // row in tile 0..63
            int m  = m0 + rl;
            float bias = g_bias[m];
            if (m < 32) {
                float* dst = g_q + ((size_t)b * C8 + m) * HW;
                #pragma unroll
                for (int na = 0; na < 4; na++) {
                    int c = n0 + wn + na * 8 + 2 * qtr;
                    float2 o;
                    o.x = acc[ma][na][half * 2 + 0] + bias;
                    o.y = acc[ma][na][half * 2 + 1] + bias;
                    *(float2*)&dst[c] = o;
                }
            } else if (wn < 64) {
                #pragma unroll
                for (int na = 0; na < 4; na++) {
                    float vx = acc[ma][na][half * 2 + 0] + bias;
                    float vy = acc[ma][na][half * 2 + 1] + bias;
                    sPool[rl][(wn >> 1) + na * 4 + qtr] = fmaxf(vx, vy);
                }
            }
        }
    }
    __syncthreads();

    // ---- epilogue phase 2: upper-half (h0+1 row) combine + pooled store ---------
    if (wn >= 64) {
        const int p0 = (n0 >> 7) * 32;   // ph * 32
        #pragma unroll
        for (int ma = 0; ma < 2; ma++) {
            #pragma unroll
            for (int half = 0; half < 2; half++) {
                int rl = wm + ma * 16 + qid + half * 8;
                int m  = m0 + rl;
                if (m < 32) continue;
                float bias = g_bias[m];
                float* dst = (m < 64)
                    ? g_kp + ((size_t)b * C8 + (m - 32)) * DOWN
                    : g_vp + ((size_t)b * C2 + (m - 64)) * DOWN;
                #pragma unroll
                for (int na = 0; na < 4; na++) {
                    int pw = ((wn - 64) >> 1) + na * 4 + qtr;
                    float vx = acc[ma][na][half * 2 + 0] + bias;
                    float vy = acc[ma][na][half * 2 + 1] + bias;
                    float pm = fmaxf(fmaxf(vx, vy), sPool[rl][pw]);
                    dst[p0 + pw] = pm;
                }
            }
        }
    }
}

// ---------------- K3: P = exp(Q @ K^T) bf16 + fused column partial sums ----------
// Tile 64l x 128j (round-13 config). Epilogue also produces per-column sums of
// the bf16-rounded P over this tile's 64 rows -> g_ps (replaces k_stats1).
__global__ __launch_bounds__(256) void k_attn() {
    const int b  = blockIdx.z;
    const int lc = blockIdx.y;          // l-chunk = 64 rows; lc in 0..63 (== NCHUNK)
    const int l0 = lc * 64;
    const int j0 = blockIdx.x * 128;

    const float* Q  = g_q  + (size_t)b * (C8 * HW);
    const float* Km = g_kp + (size_t)b * (C8 * DOWN);

    __shared__ float Qs[32][68];
    __shared__ float Ks[32][132];
    __shared__ float sRed[8][128];      // per-warp-row column partial sums

    const int tid = threadIdx.x;
    const int tx = tid & 31;
    const int ty = tid >> 5;

    #pragma unroll
    for (int it = 0; it < 2; it++) {
        int idx = tid + it * 256;
        int lr = idx >> 3, lcc = (idx & 7) * 4;
        float4 a = *(const float4*)&Q[(size_t)(l0 + lr) * 32 + lcc];
        Qs[lcc + 0][lr] = a.x; Qs[lcc + 1][lr] = a.y;
        Qs[lcc + 2][lr] = a.z; Qs[lcc + 3][lr] = a.w;
    }
    #pragma unroll
    for (int it = 0; it < 4; it++) {
        int idx = tid + it * 256;
        int jr = idx >> 3, jc = (idx & 7) * 4;
        float4 k4 = *(const float4*)&Km[(size_t)(j0 + jr) * 32 + jc];
        Ks[jc + 0][jr] = k4.x; Ks[jc + 1][jr] = k4.y;
        Ks[jc + 2][jr] = k4.z; Ks[jc + 3][jr] = k4.w;
    }
    __syncthreads();

    float acc[8][4] = {};
    #pragma unroll
    for (int d = 0; d < 32; d++) {
        float a[8], bb[4];
        *(float4*)&a[0] = *(const float4*)&Qs[d][ty * 8];
        *(float4*)&a[4] = *(const float4*)&Qs[d][ty * 8 + 4];
        *(float4*)&bb[0] = *(const float4*)&Ks[d][tx * 4];
        #pragma unroll
        for (int i = 0; i < 8; i++)
            #pragma unroll
            for (int j = 0; j < 4; j++)
                acc[i][j] += a[i] * bb[j];
    }

    // epilogue: exp -> bf16 store, and accumulate bf16-rounded column sums
    __nv_bfloat16* C = g_attn + ((size_t)b * HW + l0) * DOWN + j0;
    float csum[4] = {0.f, 0.f, 0.f, 0.f};
    #pragma unroll
    for (int i = 0; i < 8; i++) {
        __nv_bfloat16 b0 = __float2bfloat16_rn(__expf(acc[i][0]));
        __nv_bfloat16 b1 = __float2bfloat16_rn(__expf(acc[i][1]));
        __nv_bfloat16 b2 = __float2bfloat16_rn(__expf(acc[i][2]));
        __nv_bfloat16 b3 = __float2bfloat16_rn(__expf(acc[i][3]));
        csum[0] += __bfloat162float(b0);
        csum[1] += __bfloat162float(b1);
        csum[2] += __bfloat162float(b2);
        csum[3] += __bfloat162float(b3);
        __nv_bfloat162 p0 = __halves2bfloat162(b0, b1);
        __nv_bfloat162 p1 = __halves2bfloat162(b2, b3);
        uint2 o;
        o.x = *(uint32_t*)&p0;
        o.y = *(uint32_t*)&p1;
        *(uint2*)&C[(size_t)(ty * 8 + i) * DOWN + tx * 4] = o;
    }
    #pragma unroll
    for (int j = 0; j < 4; j++)
        sRed[ty][tx * 4 + j] = csum[j];
    __syncthreads();

    if (tid < 128) {
        float S = sRed[0][tid];
        #pragma unroll
        for (int t = 1; t < 8; t++) S += sRed[t][tid];
        g_ps[((size_t)b * NCHUNK + lc) * DOWN + j0 + tid] = S;
    }
}

// ---------------- K3b: merge 64 l-chunk partials per column -> 1/S ---------------
__global__ void k_stats2() {
    const int b = blockIdx.y;
    const int j = blockIdx.x * 256 + threadIdx.x;
    float S = 0.f;
    #pragma unroll 8
    for (int c = 0; c < NCHUNK; c++)
        S += g_ps[((size_t)b * NCHUNK + c) * DOWN + j];
    g_csumr[b * DOWN + j] = 1.f / S;
}

// ---------------- K4: applied = P @ (V/S) via mma.sync bf16 m16n8k16 -------------
__global__ __launch_bounds__(256, 2) void k_apply_mma() {
    __shared__ __nv_bfloat16 sP[128][40];   // [l][j in chunk]
    __shared__ __nv_bfloat16 sB[128][40];   // [c][j in chunk]

    const int b   = blockIdx.y;
    const int l0  = blockIdx.x * 128;
    const int tid = threadIdx.x;
    const int wid = tid >> 5;
    const int lane = tid & 31;
    const int qid = lane >> 2;
    const int qtr = lane & 3;
    const int wm = (wid >> 2) * 64;
    const int wn = (wid & 3) * 32;

    const __nv_bfloat16* A = g_attn + ((size_t)b * HW + l0) * DOWN;
    const float* V  = g_vp   + (size_t)b * (C2 * DOWN);
    const float* cs = g_csumr + b * DOWN;

    float acc[4][4][4] = {};

    for (int j0 = 0; j0 < DOWN; j0 += 32) {
        #pragma unroll
        for (int it = 0; it < 4; it++) {
            int idx = tid + it * 256;
            int l = idx >> 3, jq = (idx & 7) * 4;
            uint2 v = *(const uint2*)&A[(size_t)l * DOWN + j0 + jq];
            *(uint2*)&sP[l][jq] = v;
        }
        #pragma unroll
        for (int it = 0; it < 4; it++) {
            int idx = tid + it * 256;
            int c = idx & 127, j4 = idx >> 7;     // j4 in 0..7
            float4 s4 = *(const float4*)&cs[j0 + j4 * 4];
            __nv_bfloat162 p0 = __floats2bfloat162_rn(
                V[(size_t)(j0 + j4 * 4 + 0) * C2 + c] * s4.x,
                V[(size_t)(j0 + j4 * 4 + 1) * C2 + c] * s4.y);
            __nv_bfloat162 p1 = __floats2bfloat162_rn(
                V[(size_t)(j0 + j4 * 4 + 2) * C2 + c] * s4.z,
                V[(size_t)(j0 + j4 * 4 + 3) * C2 + c] * s4.w);
            uint2 o;
            o.x = *(uint32_t*)&p0;
            o.y = *(uint32_t*)&p1;
            *(uint2*)&sB[c][j4 * 4] = o;
        }
        __syncthreads();

        #pragma unroll
        for (int ks = 0; ks < 2; ks++) {
            const int kb = ks * 16;
            uint32_t bfr[4][2];
            #pragma unroll
            for (int na = 0; na < 4; na++) {
                int c = wn + na * 8 + qid;
                bfr[na][0] = *(const uint32_t*)&sB[c][kb + qtr * 2];
                bfr[na][1] = *(const uint32_t*)&sB[c][kb + 8 + qtr * 2];
            }
            #pragma unroll
            for (int ma = 0; ma < 4; ma++) {
                int r = wm + ma * 16 + qid;
                uint32_t af[4];
                af[0] = *(const uint32_t*)&sP[r    ][kb + qtr * 2];
                af[1] = *(const uint32_t*)&sP[r + 8][kb + qtr * 2];
                af[2] = *(const uint32_t*)&sP[r    ][kb + 8 + qtr * 2];
                af[3] = *(const uint32_t*)&sP[r + 8][kb + 8 + qtr * 2];
                #pragma unroll
                for (int na = 0; na < 4; na++)
                    mma_bf16(acc[ma][na], af, bfr[na]);
            }
        }
        __syncthreads();
    }

    float* O = g_app + ((size_t)b * HW + l0) * C2;
    #pragma unroll
    for (int ma = 0; ma < 4; ma++) {
        int r = wm + ma * 16 + qid;
        #pragma unroll
        for (int na = 0; na < 4; na++) {
            int c = wn + na * 8 + 2 * qtr;
            float2 lo, hi;
            lo.x = acc[ma][na][0]; lo.y = acc[ma][na][1];
            hi.x = acc[ma][na][2]; hi.y = acc[ma][na][3];
            *(float2*)&O[(size_t)r * C2 + c]       = lo;
            *(float2*)&O[(size_t)(r + 8) * C2 + c] = hi;
        }
    }
}

// ---------------- K5: out = gamma*(W2 @ applied_r + b2) + x via mma tf32 ---------
__global__ __launch_bounds__(256) void k_out_mma(const float* __restrict__ w2,
                                                 const float* __restrict__ b2,
                                                 const float* __restrict__ gamma,
                                                 const float* __restrict__ x,
                                                 float* __restrict__ out) {
    __shared__ float sA[64][36];
    __shared__ float sB[32][136];

    const int b  = blockIdx.z;
    const int m0 = blockIdx.y * 64;
    const int n0 = blockIdx.x * 128;
    const float* Bm = g_app + (size_t)b * (HW * C2);   // viewed [128][4096]

    const int tid  = threadIdx.x;
    const int wid  = tid >> 5;
    const int lane = tid & 31;
    const int qid  = lane >> 2;
    const int qtr  = lane & 3;
    const int wm   = (wid >> 2) * 32;
    const int wn   = (wid & 3) * 32;

    float acc[2][4][4] = {};

    for (int k0 = 0; k0 < C2; k0 += 32) {
        #pragma unroll
        for (int it = 0; it < 2; it++) {
            int f = tid + it * 256;
            int m = f >> 3, k4 = (f & 7) * 4;
            float4 a4 = *(const float4*)&w2[(m0 + m) * C2 + k0 + k4];
            uint32_t* dp = (uint32_t*)&sA[m][k4];
            dp[0] = f2tf32(a4.x); dp[1] = f2tf32(a4.y);
            dp[2] = f2tf32(a4.z); dp[3] = f2tf32(a4.w);
        }
        #pragma unroll
        for (int it = 0; it < 4; it++) {
            int f = tid + it * 256;
            int kk = f >> 5, n4 = (f & 31) * 4;
            float4 b4 = *(const float4*)&Bm[(size_t)(k0 + kk) * HW + n0 + n4];
            uint32_t* dp = (uint32_t*)&sB[kk][n4];
            dp[0] = f2tf32(b4.x); dp[1] = f2tf32(b4.y);
            dp[2] = f2tf32(b4.z); dp[3] = f2tf32(b4.w);
        }
        __syncthreads();

        #pragma unroll
        for (int ks = 0; ks < 4; ks++) {
            const int kk = ks * 8;
            uint32_t af[2][4], bf[4][2];
            #pragma unroll
            for (int ma = 0; ma < 2; ma++) {
                int r = wm + ma * 16 + qid;
                af[ma][0] = FU(sA[r    ][kk + qtr]);
                af[ma][1] = FU(sA[r + 8][kk + qtr]);
                af[ma][2] = FU(sA[r    ][kk + qtr + 4]);
                af[ma][3] = FU(sA[r + 8][kk + qtr + 4]);
            }
            #pragma unroll
            for (int na = 0; na < 4; na++) {
                int c = wn + na * 8 + qid;
                bf[na][0] = FU(sB[kk + qtr    ][c]);
                bf[na][1] = FU(sB[kk + qtr + 4][c]);
            }
            #pragma unroll
            for (int ma = 0; ma < 2; ma++)
                #pragma unroll
                for (int na = 0; na < 4; na++)
                    mma_tf32(acc[ma][na], af[ma], bf[na]);
        }
        __syncthreads();
    }

    const float g = __ldg(gamma);
    #pragma unroll
    for (int ma = 0; ma < 2; ma++) {
        #pragma unroll
        for (int half = 0; half < 2; half++) {
            int m = m0 + wm + ma * 16 + qid + half * 8;
            float bias = b2[m];
            #pragma unroll
            for (int na = 0; na < 4; na++) {
                int c = n0 + wn + na * 8 + 2 * qtr;
                size_t base = ((size_t)b * 256 + m) * HW + c;
                float2 xi = *(const float2*)&x[base];
                float2 o;
                o.x = g * (acc[ma][na][half * 2 + 0] + bias) + xi.x;
                o.y = g * (acc[ma][na][half * 2 + 1] + bias) + xi.y;
                *(float2*)&out[base] = o;
            }
        }
    }
}

// ---------------- launch ---------------------------------------------------------
extern "C" void kernel_launch(void* const* d_in, const int* in_sizes, int n_in,
                              void* d_out, int out_size) {
    const float* x  = (const float*)d_in[0];
    const float* qw = (const float*)d_in[1];
    const float* qb = (const float*)d_in[2];
    const float* kw = (const float*)d_in[3];
    const float* kb = (const float*)d_in[4];
    const float* vw = (const float*)d_in[5];
    const float* vb = (const float*)d_in[6];
    const float* w2 = (const float*)d_in[7];
    const float* b2 = (const float*)d_in[8];
    const float* gm = (const float*)d_in[9];
    float* out = (float*)d_out;

    k_pack<<<(MCONV * CIN + 255) / 256, 256>>>(qw, qb, kw, kb, vw, vb);
    k_conv_mma<<<dim3(HW / 128, MCONV / 64, BATCH), 256>>>(x);
    k_attn<<<dim3(DOWN / 128, HW / 64, BATCH), 256>>>();
    k_stats2<<<dim3(DOWN / 256, BATCH), 256>>>();
    k_apply_mma<<<dim3(HW / 128, BATCH), 256>>>();
    k_out_mma<<<dim3(HW / 128, 256 / 64, BATCH), 256>>>(w2, b2, gm, x, out);
}